// round 2
// baseline (speedup 1.0000x reference)
#include <cuda_runtime.h>
#include <cuda_bf16.h>
#include <cstdint>

// Problem constants (fixed by the dataset)
#define N_NODES 50000
#define N_EDGES 600000
#define DIM     128

// Scratch (allocation-free: __device__ globals)
__device__ float    g_logits[N_EDGES];   // pass1: logits; pass2 overwrites with ex
__device__ unsigned g_segmax[N_NODES];   // order-preserving uint encoding of float max
__device__ float    g_segsum[N_NODES];

// -inf encoded with the monotone float->uint map (i<0 ? ~i : i|0x80000000)
#define ENC_NEG_INF 0x007FFFFFu

__device__ __forceinline__ unsigned enc_f(float f) {
    int i = __float_as_int(f);
    return (i < 0) ? ~(unsigned)i : ((unsigned)i | 0x80000000u);
}
__device__ __forceinline__ float dec_u(unsigned u) {
    return (u & 0x80000000u) ? __int_as_float((int)(u & 0x7FFFFFFFu))
                             : __int_as_float((int)~u);
}

// ---------------------------------------------------------------------------
// Init: seg_max = enc(-inf), seg_sum = 0
// ---------------------------------------------------------------------------
__global__ void init_kernel(int n_nodes) {
    int i = blockIdx.x * blockDim.x + threadIdx.x;
    if (i < n_nodes) {
        g_segmax[i] = ENC_NEG_INF;
        g_segsum[i] = 0.0f;
    }
}

// ---------------------------------------------------------------------------
// Pass 1: one warp per edge.
//   logit = (sum_k fs*fd*hd*W_pi[k]) * sigmoid(sum_k fs*fd*W_M[k] + hd*W_M[128+k])
//   seg_max[dst] = max(seg_max[dst], logit)   (atomicMax on encoded uint)
// ---------------------------------------------------------------------------
__global__ void __launch_bounds__(256)
edge_logits_kernel(const float* __restrict__ h_v,
                   const float* __restrict__ h_d,
                   const float* __restrict__ W_pi,
                   const float* __restrict__ W_M,
                   const int*   __restrict__ src,
                   const int*   __restrict__ dst,
                   int n_edges)
{
    int gwarp = (blockIdx.x * blockDim.x + threadIdx.x) >> 5;
    int lane  = threadIdx.x & 31;
    if (gwarp >= n_edges) return;

    int s = src[gwarp];
    int d = dst[gwarp];

    const float4* fs4 = (const float4*)(h_v + (size_t)s * DIM);
    const float4* fd4 = (const float4*)(h_v + (size_t)d * DIM);
    const float4* hd4 = (const float4*)(h_d + (size_t)gwarp * DIM);
    const float4* wp4 = (const float4*)(W_pi);
    const float4* w14 = (const float4*)(W_M);
    const float4* w24 = (const float4*)(W_M + DIM);

    float4 a = fs4[lane];
    float4 b = fd4[lane];
    float4 c = hd4[lane];
    float4 wp = wp4[lane];
    float4 w1 = w14[lane];
    float4 w2 = w24[lane];

    float p0 = a.x * b.x, p1 = a.y * b.y, p2 = a.z * b.z, p3 = a.w * b.w;

    // e contribution (prod * h_d) . W_pi
    float s1 = p0 * c.x * wp.x + p1 * c.y * wp.y + p2 * c.z * wp.z + p3 * c.w * wp.w;
    // mask pre-activation: prod . W_M[0:128] + h_d . W_M[128:256]
    float s2 = p0 * w1.x + p1 * w1.y + p2 * w1.z + p3 * w1.w
             + c.x * w2.x + c.y * w2.y + c.z * w2.z + c.w * w2.w;

    #pragma unroll
    for (int o = 16; o; o >>= 1) {
        s1 += __shfl_xor_sync(0xFFFFFFFFu, s1, o);
        s2 += __shfl_xor_sync(0xFFFFFFFFu, s2, o);
    }

    if (lane == 0) {
        float sig   = 1.0f / (1.0f + __expf(-s2));
        float logit = s1 * sig;
        g_logits[gwarp] = logit;
        atomicMax(&g_segmax[d], enc_f(logit));
    }
}

// ---------------------------------------------------------------------------
// Pass 2: one thread per edge.
//   ex = exp(logit - seg_max[dst]);  seg_sum[dst] += ex
// ---------------------------------------------------------------------------
__global__ void __launch_bounds__(256)
edge_exp_kernel(const int* __restrict__ dst, int n_edges)
{
    int e = blockIdx.x * blockDim.x + threadIdx.x;
    if (e >= n_edges) return;
    int d = dst[e];
    float m = dec_u(g_segmax[d]);
    float v = expf(g_logits[e] - m);
    g_logits[e] = v;                 // reuse buffer: now holds ex
    atomicAdd(&g_segsum[d], v);
}

// ---------------------------------------------------------------------------
// Pass 3: one warp per edge.
//   a = ex / seg_sum[dst];  out[dst] += h_v[src] * a   (vector reduction)
// ---------------------------------------------------------------------------
__global__ void __launch_bounds__(256)
edge_scatter_kernel(const float* __restrict__ h_v,
                    const int*   __restrict__ src,
                    const int*   __restrict__ dst,
                    float*       __restrict__ out,
                    int n_edges)
{
    int gwarp = (blockIdx.x * blockDim.x + threadIdx.x) >> 5;
    int lane  = threadIdx.x & 31;
    if (gwarp >= n_edges) return;

    int s = src[gwarp];
    int d = dst[gwarp];
    float a = g_logits[gwarp] / g_segsum[d];

    float4 fs = ((const float4*)(h_v + (size_t)s * DIM))[lane];
    float* p = out + (size_t)d * DIM + lane * 4;

    float x = fs.x * a, y = fs.y * a, z = fs.z * a, w = fs.w * a;
    asm volatile("red.global.add.v4.f32 [%0], {%1, %2, %3, %4};"
                 :: "l"(p), "f"(x), "f"(y), "f"(z), "f"(w)
                 : "memory");
}

// ---------------------------------------------------------------------------
// Launch
// inputs: 0=h_v [N,128] f32, 1=h_d [E,128] f32, 2=W_pi [128,1] f32,
//         3=W_M [256,1] f32, 4=src [E] i32, 5=dst [E] i32
// out: [N,128] f32
// ---------------------------------------------------------------------------
extern "C" void kernel_launch(void* const* d_in, const int* in_sizes, int n_in,
                              void* d_out, int out_size)
{
    const float* h_v  = (const float*)d_in[0];
    const float* h_d  = (const float*)d_in[1];
    const float* W_pi = (const float*)d_in[2];
    const float* W_M  = (const float*)d_in[3];
    const int*   src  = (const int*)d_in[4];
    const int*   dst  = (const int*)d_in[5];
    float*       out  = (float*)d_out;

    int n_nodes = in_sizes[0] / DIM;
    int n_edges = in_sizes[1] / DIM;

    // zero output (poisoned by harness)
    cudaMemsetAsync(out, 0, (size_t)n_nodes * DIM * sizeof(float));

    init_kernel<<<(n_nodes + 255) / 256, 256>>>(n_nodes);

    // warp-per-edge: 8 warps/block
    int blocks_w = (n_edges + 7) / 8;
    edge_logits_kernel<<<blocks_w, 256>>>(h_v, h_d, W_pi, W_M, src, dst, n_edges);

    edge_exp_kernel<<<(n_edges + 255) / 256, 256>>>(dst, n_edges);

    edge_scatter_kernel<<<blocks_w, 256>>>(h_v, src, dst, out, n_edges);
}

// round 3
// speedup vs baseline: 1.2675x; 1.2675x over previous
#include <cuda_runtime.h>
#include <cuda_bf16.h>
#include <cstdint>

#define N_NODES 50000
#define N_EDGES 600000
#define DIM     128
#define SCAN_BLOCKS 256          // >= ceil(N_NODES/256) = 196
#define MAX_SMEM_DEG 96

// ----- scratch (allocation-free __device__ globals) -----
__device__ int   g_deg[N_NODES];
__device__ int   g_off[N_NODES + 1];
__device__ int   g_cur[N_NODES];
__device__ int   g_bsum[SCAN_BLOCKS];
__device__ int   g_pedge[N_EDGES];   // CSR-ordered edge id (for h_d row)
__device__ int   g_psrc[N_EDGES];    // CSR-ordered src node id
__device__ float g_ex[N_EDGES];      // fallback logit/ex storage for deg > MAX_SMEM_DEG

// ---------------------------------------------------------------------------
// CSR build
// ---------------------------------------------------------------------------
__global__ void zero_deg_kernel(int n_nodes) {
    int i = blockIdx.x * blockDim.x + threadIdx.x;
    if (i < n_nodes) g_deg[i] = 0;
}

__global__ void hist_kernel(const int* __restrict__ dst, int n_edges) {
    int e = blockIdx.x * blockDim.x + threadIdx.x;
    if (e < n_edges) atomicAdd(&g_deg[dst[e]], 1);
}

// block-local exclusive scan; block totals to g_bsum
__global__ void scanA_kernel(int n_nodes) {
    __shared__ int sm[256];
    int t = threadIdx.x, b = blockIdx.x;
    int idx = b * 256 + t;
    int v = (idx < n_nodes) ? g_deg[idx] : 0;
    sm[t] = v;
    __syncthreads();
    #pragma unroll
    for (int off = 1; off < 256; off <<= 1) {
        int add = (t >= off) ? sm[t - off] : 0;
        __syncthreads();
        sm[t] += add;
        __syncthreads();
    }
    int incl = sm[t];
    if (idx < n_nodes) g_off[idx] = incl - v;   // block-local exclusive
    if (t == 255) g_bsum[b] = incl;             // block total
}

// exclusive scan of block totals (single block)
__global__ void scanB_kernel(int nblocks) {
    __shared__ int sm[SCAN_BLOCKS];
    int t = threadIdx.x;
    int v = (t < nblocks) ? g_bsum[t] : 0;
    sm[t] = v;
    __syncthreads();
    #pragma unroll
    for (int off = 1; off < SCAN_BLOCKS; off <<= 1) {
        int add = (t >= off) ? sm[t - off] : 0;
        __syncthreads();
        sm[t] += add;
        __syncthreads();
    }
    g_bsum[t] = sm[t] - v;                      // exclusive
}

__global__ void scanC_kernel(int n_nodes, int n_edges) {
    int idx = blockIdx.x * blockDim.x + threadIdx.x;
    if (idx < n_nodes) {
        int o = g_off[idx] + g_bsum[idx >> 8];
        g_off[idx] = o;
        g_cur[idx] = o;
    }
    if (idx == 0) g_off[n_nodes] = n_edges;
}

__global__ void scatter_perm_kernel(const int* __restrict__ src,
                                    const int* __restrict__ dst, int n_edges) {
    int e = blockIdx.x * blockDim.x + threadIdx.x;
    if (e >= n_edges) return;
    int pos = atomicAdd(&g_cur[dst[e]], 1);
    g_pedge[pos] = e;
    g_psrc[pos]  = src[e];
}

// ---------------------------------------------------------------------------
// Fused per-node kernel: warp per dst node.
//   loop1: per incoming edge compute logit (warp dot-products), track max
//   loop2: ex = exp(l - max), total (lane-parallel over stored logits)
//   loop3: acc += h_v[src] * ex/total; single coalesced store of out row
// ---------------------------------------------------------------------------
__global__ void __launch_bounds__(256)
fused_node_kernel(const float* __restrict__ h_v,
                  const float* __restrict__ h_d,
                  const float* __restrict__ W_pi,
                  const float* __restrict__ W_M,
                  float*       __restrict__ out,
                  int n_nodes)
{
    __shared__ float s_l[8][MAX_SMEM_DEG];

    int gwarp = (blockIdx.x * blockDim.x + threadIdx.x) >> 5;
    int lane  = threadIdx.x & 31;
    int w     = (threadIdx.x >> 5);
    if (gwarp >= n_nodes) return;

    int beg = g_off[gwarp];
    int end = g_off[gwarp + 1];
    int deg = end - beg;

    const float4* hv4 = (const float4*)h_v;
    const float4* hd4 = (const float4*)h_d;

    // out row always written (segment_sum semantics: empty segment -> 0)
    float4 acc = make_float4(0.f, 0.f, 0.f, 0.f);

    if (deg > 0) {
        float4 fd = hv4[(size_t)gwarp * 32 + lane];
        float4 wp = ((const float4*)W_pi)[lane];
        float4 w1 = ((const float4*)W_M)[lane];
        float4 w2 = ((const float4*)(W_M + DIM))[lane];
        // premultiply the node-constant factors
        float4 c1 = make_float4(fd.x * wp.x, fd.y * wp.y, fd.z * wp.z, fd.w * wp.w);
        float4 c2 = make_float4(fd.x * w1.x, fd.y * w1.y, fd.z * w1.z, fd.w * w1.w);

        bool big = (deg > MAX_SMEM_DEG);
        float mx = -3.4e38f;

        // ---- loop 1: logits ----
        for (int i = 0; i < deg; i++) {
            int p = beg + i;
            int s = g_psrc[p];
            int e = g_pedge[p];
            float4 fs = hv4[(size_t)s * 32 + lane];
            float4 hd = hd4[(size_t)e * 32 + lane];

            // s1 = sum fs*fd*hd*W_pi ; s2 = sum fs*fd*W_M1 + hd*W_M2
            float s1 = fs.x * hd.x * c1.x + fs.y * hd.y * c1.y
                     + fs.z * hd.z * c1.z + fs.w * hd.w * c1.w;
            float s2 = fs.x * c2.x + fs.y * c2.y + fs.z * c2.z + fs.w * c2.w
                     + hd.x * w2.x + hd.y * w2.y + hd.z * w2.z + hd.w * w2.w;

            #pragma unroll
            for (int o = 16; o; o >>= 1) {
                s1 += __shfl_xor_sync(0xFFFFFFFFu, s1, o);
                s2 += __shfl_xor_sync(0xFFFFFFFFu, s2, o);
            }
            float sig = 1.0f / (1.0f + __expf(-s2));
            float l   = s1 * sig;
            mx = fmaxf(mx, l);
            if (lane == 0) {
                if (big) g_ex[p] = l; else s_l[w][i] = l;
            }
        }
        __syncwarp();

        // ---- loop 2: exp + sum (lane-parallel) ----
        float psum = 0.f;
        for (int i = lane; i < deg; i += 32) {
            float l = big ? g_ex[beg + i] : s_l[w][i];
            float ev = __expf(l - mx);
            if (big) g_ex[beg + i] = ev; else s_l[w][i] = ev;
            psum += ev;
        }
        #pragma unroll
        for (int o = 16; o; o >>= 1)
            psum += __shfl_xor_sync(0xFFFFFFFFu, psum, o);
        float inv = 1.0f / psum;
        __syncwarp();

        // ---- loop 3: weighted aggregate ----
        for (int i = 0; i < deg; i++) {
            int p = beg + i;
            float a = (big ? g_ex[p] : s_l[w][i]) * inv;
            int s = g_psrc[p];
            float4 fs = hv4[(size_t)s * 32 + lane];
            acc.x += fs.x * a;
            acc.y += fs.y * a;
            acc.z += fs.z * a;
            acc.w += fs.w * a;
        }
    }

    ((float4*)out)[(size_t)gwarp * 32 + lane] = acc;
}

// ---------------------------------------------------------------------------
// Launch
// inputs: 0=h_v [N,128] f32, 1=h_d [E,128] f32, 2=W_pi [128,1] f32,
//         3=W_M [256,1] f32, 4=src [E] i32, 5=dst [E] i32 ; out [N,128] f32
// ---------------------------------------------------------------------------
extern "C" void kernel_launch(void* const* d_in, const int* in_sizes, int n_in,
                              void* d_out, int out_size)
{
    const float* h_v  = (const float*)d_in[0];
    const float* h_d  = (const float*)d_in[1];
    const float* W_pi = (const float*)d_in[2];
    const float* W_M  = (const float*)d_in[3];
    const int*   src  = (const int*)d_in[4];
    const int*   dst  = (const int*)d_in[5];
    float*       out  = (float*)d_out;

    int n_nodes = in_sizes[0] / DIM;
    int n_edges = in_sizes[1] / DIM;
    int nblocks_scan = (n_nodes + 255) / 256;

    zero_deg_kernel<<<(n_nodes + 255) / 256, 256>>>(n_nodes);
    hist_kernel<<<(n_edges + 255) / 256, 256>>>(dst, n_edges);
    scanA_kernel<<<nblocks_scan, 256>>>(n_nodes);
    scanB_kernel<<<1, SCAN_BLOCKS>>>(nblocks_scan);
    scanC_kernel<<<(n_nodes + 255) / 256, 256>>>(n_nodes, n_edges);
    scatter_perm_kernel<<<(n_edges + 255) / 256, 256>>>(src, dst, n_edges);

    // warp per node, 8 warps/block
    int blocks = (n_nodes + 7) / 8;
    fused_node_kernel<<<blocks, 256>>>(h_v, h_d, W_pi, W_M, out, n_nodes);
}

// round 4
// speedup vs baseline: 1.4159x; 1.1171x over previous
#include <cuda_runtime.h>
#include <cuda_bf16.h>
#include <cstdint>

#define N_NODES 50000
#define N_EDGES 600000
#define DIM     128
#define SCAN_BLOCKS 256          // >= ceil(N_NODES/256) = 196
#define MAX_SMEM_DEG 96

// ----- scratch (allocation-free __device__ globals) -----
__device__ int   g_deg[N_NODES];
__device__ int   g_off[N_NODES + 1];
__device__ int   g_cur[N_NODES];
__device__ int   g_pedge[N_EDGES];   // CSR-ordered original edge id (h_d row)
__device__ int   g_psrc[N_EDGES];    // CSR-ordered src node id
__device__ float g_ex[N_EDGES];      // spill storage for deg > MAX_SMEM_DEG
__device__ int   g_scan_flag[SCAN_BLOCKS];  // 0=none 1=agg 2=inclusive
__device__ int   g_scan_agg[SCAN_BLOCKS];
__device__ int   g_scan_inc[SCAN_BLOCKS];
__device__ int   g_work;             // dynamic node queue

// ---------------------------------------------------------------------------
// zero: degrees, scan flags, work counter
// ---------------------------------------------------------------------------
__global__ void zero_kernel(int n_nodes) {
    int i = blockIdx.x * blockDim.x + threadIdx.x;
    if (i < n_nodes) g_deg[i] = 0;
    if (i < SCAN_BLOCKS) g_scan_flag[i] = 0;
    if (i == 0) g_work = 0;
}

__global__ void hist_kernel(const int* __restrict__ dst, int n_edges) {
    int e = blockIdx.x * blockDim.x + threadIdx.x;
    if (e < n_edges) atomicAdd(&g_deg[dst[e]], 1);
}

// ---------------------------------------------------------------------------
// Single-pass exclusive scan (decoupled lookback). All blocks co-resident.
// ---------------------------------------------------------------------------
__global__ void __launch_bounds__(256)
scan_kernel(int n_nodes, int n_edges) {
    int b = blockIdx.x, t = threadIdx.x;
    int idx = b * 256 + t;
    int lane = t & 31, w = t >> 5;

    int v = (idx < n_nodes) ? g_deg[idx] : 0;

    // warp inclusive scan
    int x = v;
    #pragma unroll
    for (int o = 1; o < 32; o <<= 1) {
        int y = __shfl_up_sync(0xFFFFFFFFu, x, o);
        if (lane >= o) x += y;
    }
    __shared__ int wsum[8];
    if (lane == 31) wsum[w] = x;
    __syncthreads();
    if (w == 0) {
        int s = (lane < 8) ? wsum[lane] : 0;
        #pragma unroll
        for (int o = 1; o < 8; o <<= 1) {
            int y = __shfl_up_sync(0xFFFFFFFFu, s, o);
            if (lane >= o) s += y;
        }
        if (lane < 8) wsum[lane] = s;
    }
    __syncthreads();
    int incl = x + ((w > 0) ? wsum[w - 1] : 0);
    int block_total = wsum[7];

    __shared__ int s_prefix;
    if (t == 0) {
        if (b == 0) {
            g_scan_inc[0] = block_total;
            __threadfence();
            atomicExch(&g_scan_flag[0], 2);
            s_prefix = 0;
        } else {
            g_scan_agg[b] = block_total;
            __threadfence();
            atomicExch(&g_scan_flag[b], 1);
            int sum = 0;
            for (int j = b - 1; j >= 0; j--) {
                int f;
                do { f = atomicAdd(&g_scan_flag[j], 0); } while (f == 0);
                if (f == 2) { sum += atomicAdd(&g_scan_inc[j], 0); break; }
                sum += atomicAdd(&g_scan_agg[j], 0);
            }
            g_scan_inc[b] = sum + block_total;
            __threadfence();
            atomicExch(&g_scan_flag[b], 2);
            s_prefix = sum;
        }
    }
    __syncthreads();

    int excl = s_prefix + incl - v;
    if (idx < n_nodes) { g_off[idx] = excl; g_cur[idx] = excl; }
    if (idx == n_nodes) g_off[n_nodes] = n_edges;
}

__global__ void scatter_perm_kernel(const int* __restrict__ src,
                                    const int* __restrict__ dst, int n_edges) {
    int e = blockIdx.x * blockDim.x + threadIdx.x;
    if (e >= n_edges) return;
    int pos = atomicAdd(&g_cur[dst[e]], 1);
    g_pedge[pos] = e;
    g_psrc[pos]  = src[e];
}

// ---------------------------------------------------------------------------
// Fused per-node kernel: warp grabs nodes from a dynamic queue.
// ---------------------------------------------------------------------------
__global__ void __launch_bounds__(256)
fused_node_kernel(const float* __restrict__ h_v,
                  const float* __restrict__ h_d,
                  const float* __restrict__ W_pi,
                  const float* __restrict__ W_M,
                  float*       __restrict__ out,
                  int n_nodes)
{
    __shared__ float s_l[8][MAX_SMEM_DEG];

    int lane = threadIdx.x & 31;
    int w    = threadIdx.x >> 5;

    const float4* hv4 = (const float4*)h_v;
    const float4* hd4 = (const float4*)h_d;
    float4 wp = ((const float4*)W_pi)[lane];
    float4 w1 = ((const float4*)W_M)[lane];
    float4 w2 = ((const float4*)(W_M + DIM))[lane];

    while (true) {
        int node;
        if (lane == 0) node = atomicAdd(&g_work, 1);
        node = __shfl_sync(0xFFFFFFFFu, node, 0);
        if (node >= n_nodes) break;

        int beg = g_off[node];
        int deg = g_off[node + 1] - beg;

        float4 acc = make_float4(0.f, 0.f, 0.f, 0.f);

        if (deg > 0) {
            float4 fd = hv4[(size_t)node * 32 + lane];
            float4 c1 = make_float4(fd.x * wp.x, fd.y * wp.y, fd.z * wp.z, fd.w * wp.w);
            float4 c2 = make_float4(fd.x * w1.x, fd.y * w1.y, fd.z * w1.z, fd.w * w1.w);

            bool big = (deg > MAX_SMEM_DEG);
            float mx = -3.4e38f;

            // ---- loop 1: logits, 2 edges per iteration ----
            int i = 0;
            for (; i + 2 <= deg; i += 2) {
                int p0 = beg + i, p1 = beg + i + 1;
                int sA = g_psrc[p0],  sB = g_psrc[p1];
                int eA = g_pedge[p0], eB = g_pedge[p1];
                float4 fsA = hv4[(size_t)sA * 32 + lane];
                float4 hdA = hd4[(size_t)eA * 32 + lane];
                float4 fsB = hv4[(size_t)sB * 32 + lane];
                float4 hdB = hd4[(size_t)eB * 32 + lane];

                float a1 = fsA.x * hdA.x * c1.x + fsA.y * hdA.y * c1.y
                         + fsA.z * hdA.z * c1.z + fsA.w * hdA.w * c1.w;
                float a2 = fsA.x * c2.x + fsA.y * c2.y + fsA.z * c2.z + fsA.w * c2.w
                         + hdA.x * w2.x + hdA.y * w2.y + hdA.z * w2.z + hdA.w * w2.w;
                float b1 = fsB.x * hdB.x * c1.x + fsB.y * hdB.y * c1.y
                         + fsB.z * hdB.z * c1.z + fsB.w * hdB.w * c1.w;
                float b2 = fsB.x * c2.x + fsB.y * c2.y + fsB.z * c2.z + fsB.w * c2.w
                         + hdB.x * w2.x + hdB.y * w2.y + hdB.z * w2.z + hdB.w * w2.w;

                #pragma unroll
                for (int o = 16; o; o >>= 1) {
                    a1 += __shfl_xor_sync(0xFFFFFFFFu, a1, o);
                    a2 += __shfl_xor_sync(0xFFFFFFFFu, a2, o);
                    b1 += __shfl_xor_sync(0xFFFFFFFFu, b1, o);
                    b2 += __shfl_xor_sync(0xFFFFFFFFu, b2, o);
                }
                float lA = a1 * (1.0f / (1.0f + __expf(-a2)));
                float lB = b1 * (1.0f / (1.0f + __expf(-b2)));
                mx = fmaxf(mx, fmaxf(lA, lB));
                if (lane == 0) {
                    if (big) { g_ex[p0] = lA; g_ex[p1] = lB; }
                    else     { s_l[w][i] = lA; s_l[w][i + 1] = lB; }
                }
            }
            if (i < deg) {  // tail edge
                int p0 = beg + i;
                int sA = g_psrc[p0], eA = g_pedge[p0];
                float4 fsA = hv4[(size_t)sA * 32 + lane];
                float4 hdA = hd4[(size_t)eA * 32 + lane];
                float a1 = fsA.x * hdA.x * c1.x + fsA.y * hdA.y * c1.y
                         + fsA.z * hdA.z * c1.z + fsA.w * hdA.w * c1.w;
                float a2 = fsA.x * c2.x + fsA.y * c2.y + fsA.z * c2.z + fsA.w * c2.w
                         + hdA.x * w2.x + hdA.y * w2.y + hdA.z * w2.z + hdA.w * w2.w;
                #pragma unroll
                for (int o = 16; o; o >>= 1) {
                    a1 += __shfl_xor_sync(0xFFFFFFFFu, a1, o);
                    a2 += __shfl_xor_sync(0xFFFFFFFFu, a2, o);
                }
                float lA = a1 * (1.0f / (1.0f + __expf(-a2)));
                mx = fmaxf(mx, lA);
                if (lane == 0) {
                    if (big) g_ex[p0] = lA; else s_l[w][i] = lA;
                }
            }
            __syncwarp();

            // ---- loop 2: exp + sum (lane-parallel) ----
            float psum = 0.f;
            for (int j = lane; j < deg; j += 32) {
                float l = big ? g_ex[beg + j] : s_l[w][j];
                float ev = __expf(l - mx);
                if (big) g_ex[beg + j] = ev; else s_l[w][j] = ev;
                psum += ev;
            }
            #pragma unroll
            for (int o = 16; o; o >>= 1)
                psum += __shfl_xor_sync(0xFFFFFFFFu, psum, o);
            float inv = 1.0f / psum;
            __syncwarp();

            // ---- loop 3: weighted aggregate, 4 edges per iteration ----
            int k = 0;
            for (; k + 4 <= deg; k += 4) {
                int p = beg + k;
                float aA = (big ? g_ex[p]     : s_l[w][k])     * inv;
                float aB = (big ? g_ex[p + 1] : s_l[w][k + 1]) * inv;
                float aC = (big ? g_ex[p + 2] : s_l[w][k + 2]) * inv;
                float aD = (big ? g_ex[p + 3] : s_l[w][k + 3]) * inv;
                float4 fA = hv4[(size_t)g_psrc[p]     * 32 + lane];
                float4 fB = hv4[(size_t)g_psrc[p + 1] * 32 + lane];
                float4 fC = hv4[(size_t)g_psrc[p + 2] * 32 + lane];
                float4 fD = hv4[(size_t)g_psrc[p + 3] * 32 + lane];
                acc.x += fA.x * aA + fB.x * aB + fC.x * aC + fD.x * aD;
                acc.y += fA.y * aA + fB.y * aB + fC.y * aC + fD.y * aD;
                acc.z += fA.z * aA + fB.z * aB + fC.z * aC + fD.z * aD;
                acc.w += fA.w * aA + fB.w * aB + fC.w * aC + fD.w * aD;
            }
            for (; k < deg; k++) {
                int p = beg + k;
                float a = (big ? g_ex[p] : s_l[w][k]) * inv;
                float4 f = hv4[(size_t)g_psrc[p] * 32 + lane];
                acc.x += f.x * a; acc.y += f.y * a;
                acc.z += f.z * a; acc.w += f.w * a;
            }
            __syncwarp();   // protect s_l before next node's loop1
        }

        ((float4*)out)[(size_t)node * 32 + lane] = acc;
    }
}

// ---------------------------------------------------------------------------
// Launch
// inputs: 0=h_v [N,128] f32, 1=h_d [E,128] f32, 2=W_pi [128,1] f32,
//         3=W_M [256,1] f32, 4=src [E] i32, 5=dst [E] i32 ; out [N,128] f32
// ---------------------------------------------------------------------------
extern "C" void kernel_launch(void* const* d_in, const int* in_sizes, int n_in,
                              void* d_out, int out_size)
{
    const float* h_v  = (const float*)d_in[0];
    const float* h_d  = (const float*)d_in[1];
    const float* W_pi = (const float*)d_in[2];
    const float* W_M  = (const float*)d_in[3];
    const int*   src  = (const int*)d_in[4];
    const int*   dst  = (const int*)d_in[5];
    float*       out  = (float*)d_out;

    int n_nodes = in_sizes[0] / DIM;
    int n_edges = in_sizes[1] / DIM;
    int node_blocks = (n_nodes + 255) / 256;

    zero_kernel<<<node_blocks, 256>>>(n_nodes);
    hist_kernel<<<(n_edges + 255) / 256, 256>>>(dst, n_edges);
    scan_kernel<<<node_blocks, 256>>>(n_nodes, n_edges);
    scatter_perm_kernel<<<(n_edges + 255) / 256, 256>>>(src, dst, n_edges);

    // dynamic work queue: grid just needs to fill the machine
    fused_node_kernel<<<1024, 256>>>(h_v, h_d, W_pi, W_M, out, n_nodes);
}

// round 5
// speedup vs baseline: 1.4614x; 1.0321x over previous
#include <cuda_runtime.h>
#include <cuda_bf16.h>
#include <cstdint>

#define N_NODES 50000
#define N_EDGES 600000
#define DIM     128
#define SCAN_BLOCKS 256          // >= ceil(N_NODES/256) = 196

// ----- scratch (allocation-free __device__ globals) -----
__device__ int   g_deg[N_NODES];
__device__ int   g_off[N_NODES + 1];
__device__ int   g_rank[N_EDGES];      // intra-segment rank of each edge
__device__ int2  g_pidx[N_EDGES];      // CSR-ordered {src node, original edge id}
__device__ int   g_scan_flag[SCAN_BLOCKS];  // 0=none 1=agg 2=inclusive
__device__ int   g_scan_agg[SCAN_BLOCKS];
__device__ int   g_scan_inc[SCAN_BLOCKS];
__device__ int   g_work;               // dynamic node queue

// ---------------------------------------------------------------------------
// zero: degrees, scan flags, work counter
// ---------------------------------------------------------------------------
__global__ void zero_kernel(int n_nodes) {
    int i = blockIdx.x * blockDim.x + threadIdx.x;
    if (i < n_nodes) g_deg[i] = 0;
    if (i < SCAN_BLOCKS) g_scan_flag[i] = 0;
    if (i == 0) g_work = 0;
}

// histogram + record intra-segment rank (the atomic pays for both)
__global__ void hist_kernel(const int* __restrict__ dst, int n_edges) {
    int e = blockIdx.x * blockDim.x + threadIdx.x;
    if (e < n_edges) g_rank[e] = atomicAdd(&g_deg[dst[e]], 1);
}

// ---------------------------------------------------------------------------
// Single-pass exclusive scan (decoupled lookback). All 196 blocks co-resident.
// ---------------------------------------------------------------------------
__global__ void __launch_bounds__(256)
scan_kernel(int n_nodes, int n_edges) {
    int b = blockIdx.x, t = threadIdx.x;
    int idx = b * 256 + t;
    int lane = t & 31, w = t >> 5;

    int v = (idx < n_nodes) ? g_deg[idx] : 0;

    int x = v;
    #pragma unroll
    for (int o = 1; o < 32; o <<= 1) {
        int y = __shfl_up_sync(0xFFFFFFFFu, x, o);
        if (lane >= o) x += y;
    }
    __shared__ int wsum[8];
    if (lane == 31) wsum[w] = x;
    __syncthreads();
    if (w == 0) {
        int s = (lane < 8) ? wsum[lane] : 0;
        #pragma unroll
        for (int o = 1; o < 8; o <<= 1) {
            int y = __shfl_up_sync(0xFFFFFFFFu, s, o);
            if (lane >= o) s += y;
        }
        if (lane < 8) wsum[lane] = s;
    }
    __syncthreads();
    int incl = x + ((w > 0) ? wsum[w - 1] : 0);
    int block_total = wsum[7];

    __shared__ int s_prefix;
    if (t == 0) {
        if (b == 0) {
            g_scan_inc[0] = block_total;
            __threadfence();
            atomicExch(&g_scan_flag[0], 2);
            s_prefix = 0;
        } else {
            g_scan_agg[b] = block_total;
            __threadfence();
            atomicExch(&g_scan_flag[b], 1);
            int sum = 0;
            for (int j = b - 1; j >= 0; j--) {
                int f;
                do { f = atomicAdd(&g_scan_flag[j], 0); } while (f == 0);
                if (f == 2) { sum += atomicAdd(&g_scan_inc[j], 0); break; }
                sum += atomicAdd(&g_scan_agg[j], 0);
            }
            g_scan_inc[b] = sum + block_total;
            __threadfence();
            atomicExch(&g_scan_flag[b], 2);
            s_prefix = sum;
        }
    }
    __syncthreads();

    int excl = s_prefix + incl - v;
    if (idx < n_nodes) g_off[idx] = excl;
    if (idx == n_nodes) g_off[n_nodes] = n_edges;
}

// atomic-free permutation scatter: pos = off[dst] + rank
__global__ void __launch_bounds__(256)
scatter_perm_kernel(const int* __restrict__ src,
                    const int* __restrict__ dst, int n_edges) {
    int e = blockIdx.x * blockDim.x + threadIdx.x;
    if (e >= n_edges) return;
    int pos = g_off[dst[e]] + g_rank[e];
    g_pidx[pos] = make_int2(src[e], e);
}

// ---------------------------------------------------------------------------
// Fused per-node kernel with ONLINE softmax: one pass over incoming edges.
//   running (mx, sum, acc); acc rescaled on max update. fs reused from regs.
// ---------------------------------------------------------------------------
__global__ void __launch_bounds__(256)
fused_node_kernel(const float* __restrict__ h_v,
                  const float* __restrict__ h_d,
                  const float* __restrict__ W_pi,
                  const float* __restrict__ W_M,
                  float*       __restrict__ out,
                  int n_nodes)
{
    int lane = threadIdx.x & 31;

    const float4* hv4 = (const float4*)h_v;
    const float4* hd4 = (const float4*)h_d;
    float4 wp = ((const float4*)W_pi)[lane];
    float4 w1 = ((const float4*)W_M)[lane];
    float4 w2 = ((const float4*)(W_M + DIM))[lane];

    while (true) {
        int node;
        if (lane == 0) node = atomicAdd(&g_work, 1);
        node = __shfl_sync(0xFFFFFFFFu, node, 0);
        if (node >= n_nodes) break;

        int beg = g_off[node];
        int deg = g_off[node + 1] - beg;

        float4 acc = make_float4(0.f, 0.f, 0.f, 0.f);
        float mx = -3.4e38f, sum = 0.f;

        if (deg > 0) {
            float4 fd = hv4[(size_t)node * 32 + lane];
            float4 c1 = make_float4(fd.x * wp.x, fd.y * wp.y, fd.z * wp.z, fd.w * wp.w);
            float4 c2 = make_float4(fd.x * w1.x, fd.y * w1.y, fd.z * w1.z, fd.w * w1.w);

            int i = 0;
            for (; i + 2 <= deg; i += 2) {
                int2 pA = g_pidx[beg + i];
                int2 pB = g_pidx[beg + i + 1];
                float4 fsA = hv4[(size_t)pA.x * 32 + lane];
                float4 hdA = hd4[(size_t)pA.y * 32 + lane];
                float4 fsB = hv4[(size_t)pB.x * 32 + lane];
                float4 hdB = hd4[(size_t)pB.y * 32 + lane];

                float a1 = fsA.x * hdA.x * c1.x + fsA.y * hdA.y * c1.y
                         + fsA.z * hdA.z * c1.z + fsA.w * hdA.w * c1.w;
                float a2 = fsA.x * c2.x + fsA.y * c2.y + fsA.z * c2.z + fsA.w * c2.w
                         + hdA.x * w2.x + hdA.y * w2.y + hdA.z * w2.z + hdA.w * w2.w;
                float b1 = fsB.x * hdB.x * c1.x + fsB.y * hdB.y * c1.y
                         + fsB.z * hdB.z * c1.z + fsB.w * hdB.w * c1.w;
                float b2 = fsB.x * c2.x + fsB.y * c2.y + fsB.z * c2.z + fsB.w * c2.w
                         + hdB.x * w2.x + hdB.y * w2.y + hdB.z * w2.z + hdB.w * w2.w;

                #pragma unroll
                for (int o = 16; o; o >>= 1) {
                    a1 += __shfl_xor_sync(0xFFFFFFFFu, a1, o);
                    a2 += __shfl_xor_sync(0xFFFFFFFFu, a2, o);
                    b1 += __shfl_xor_sync(0xFFFFFFFFu, b1, o);
                    b2 += __shfl_xor_sync(0xFFFFFFFFu, b2, o);
                }
                float lA = a1 * (1.0f / (1.0f + __expf(-a2)));
                float lB = b1 * (1.0f / (1.0f + __expf(-b2)));

                float m2 = fmaxf(mx, fmaxf(lA, lB));
                float sc = __expf(mx - m2);            // 0 on first iter
                float eA = __expf(lA - m2);
                float eB = __expf(lB - m2);
                sum = sum * sc + eA + eB;
                acc.x = acc.x * sc + fsA.x * eA + fsB.x * eB;
                acc.y = acc.y * sc + fsA.y * eA + fsB.y * eB;
                acc.z = acc.z * sc + fsA.z * eA + fsB.z * eB;
                acc.w = acc.w * sc + fsA.w * eA + fsB.w * eB;
                mx = m2;
            }
            if (i < deg) {  // tail edge
                int2 pA = g_pidx[beg + i];
                float4 fsA = hv4[(size_t)pA.x * 32 + lane];
                float4 hdA = hd4[(size_t)pA.y * 32 + lane];
                float a1 = fsA.x * hdA.x * c1.x + fsA.y * hdA.y * c1.y
                         + fsA.z * hdA.z * c1.z + fsA.w * hdA.w * c1.w;
                float a2 = fsA.x * c2.x + fsA.y * c2.y + fsA.z * c2.z + fsA.w * c2.w
                         + hdA.x * w2.x + hdA.y * w2.y + hdA.z * w2.z + hdA.w * w2.w;
                #pragma unroll
                for (int o = 16; o; o >>= 1) {
                    a1 += __shfl_xor_sync(0xFFFFFFFFu, a1, o);
                    a2 += __shfl_xor_sync(0xFFFFFFFFu, a2, o);
                }
                float lA = a1 * (1.0f / (1.0f + __expf(-a2)));
                float m2 = fmaxf(mx, lA);
                float sc = __expf(mx - m2);
                float eA = __expf(lA - m2);
                sum = sum * sc + eA;
                acc.x = acc.x * sc + fsA.x * eA;
                acc.y = acc.y * sc + fsA.y * eA;
                acc.z = acc.z * sc + fsA.z * eA;
                acc.w = acc.w * sc + fsA.w * eA;
            }

            float inv = 1.0f / sum;
            acc.x *= inv; acc.y *= inv; acc.z *= inv; acc.w *= inv;
        }

        ((float4*)out)[(size_t)node * 32 + lane] = acc;
    }
}

// ---------------------------------------------------------------------------
// Launch
// inputs: 0=h_v [N,128] f32, 1=h_d [E,128] f32, 2=W_pi [128,1] f32,
//         3=W_M [256,1] f32, 4=src [E] i32, 5=dst [E] i32 ; out [N,128] f32
// ---------------------------------------------------------------------------
extern "C" void kernel_launch(void* const* d_in, const int* in_sizes, int n_in,
                              void* d_out, int out_size)
{
    const float* h_v  = (const float*)d_in[0];
    const float* h_d  = (const float*)d_in[1];
    const float* W_pi = (const float*)d_in[2];
    const float* W_M  = (const float*)d_in[3];
    const int*   src  = (const int*)d_in[4];
    const int*   dst  = (const int*)d_in[5];
    float*       out  = (float*)d_out;

    int n_nodes = in_sizes[0] / DIM;
    int n_edges = in_sizes[1] / DIM;
    int node_blocks = (n_nodes + 255) / 256;

    zero_kernel<<<node_blocks, 256>>>(n_nodes);
    hist_kernel<<<(n_edges + 255) / 256, 256>>>(dst, n_edges);
    scan_kernel<<<node_blocks, 256>>>(n_nodes, n_edges);
    scatter_perm_kernel<<<(n_edges + 255) / 256, 256>>>(src, dst, n_edges);

    fused_node_kernel<<<1024, 256>>>(h_v, h_d, W_pi, W_M, out, n_nodes);
}

// round 6
// speedup vs baseline: 1.4970x; 1.0243x over previous
#include <cuda_runtime.h>
#include <cuda_bf16.h>
#include <cstdint>

#define N_NODES 50000
#define N_EDGES 600000
#define DIM     128
#define SCAN_BLOCKS 256          // >= ceil(N_NODES/256) = 196

// ----- scratch (allocation-free __device__ globals) -----
__device__ int   g_deg[N_NODES];
__device__ int   g_off[N_NODES + 1];
__device__ int   g_rank[N_EDGES];      // intra-segment rank of each edge
__device__ int2  g_pidx[N_EDGES];      // CSR-ordered {src node, original edge id}
__device__ int   g_scan_flag[SCAN_BLOCKS];
__device__ int   g_scan_agg[SCAN_BLOCKS];
__device__ int   g_scan_inc[SCAN_BLOCKS];
__device__ int   g_work;               // dynamic node queue

// ---------------------------------------------------------------------------
__global__ void zero_kernel(int n_nodes) {
    int i = blockIdx.x * blockDim.x + threadIdx.x;
    if (i < n_nodes) g_deg[i] = 0;
    if (i < SCAN_BLOCKS) g_scan_flag[i] = 0;
    if (i == 0) g_work = 0;
}

// histogram + record intra-segment rank (the atomic pays for both)
__global__ void hist_kernel(const int* __restrict__ dst, int n_edges) {
    int e = blockIdx.x * blockDim.x + threadIdx.x;
    if (e < n_edges) g_rank[e] = atomicAdd(&g_deg[dst[e]], 1);
}

// ---------------------------------------------------------------------------
// Single-pass exclusive scan (decoupled lookback). All 196 blocks co-resident.
// ---------------------------------------------------------------------------
__global__ void __launch_bounds__(256)
scan_kernel(int n_nodes, int n_edges) {
    int b = blockIdx.x, t = threadIdx.x;
    int idx = b * 256 + t;
    int lane = t & 31, w = t >> 5;

    int v = (idx < n_nodes) ? g_deg[idx] : 0;

    int x = v;
    #pragma unroll
    for (int o = 1; o < 32; o <<= 1) {
        int y = __shfl_up_sync(0xFFFFFFFFu, x, o);
        if (lane >= o) x += y;
    }
    __shared__ int wsum[8];
    if (lane == 31) wsum[w] = x;
    __syncthreads();
    if (w == 0) {
        int s = (lane < 8) ? wsum[lane] : 0;
        #pragma unroll
        for (int o = 1; o < 8; o <<= 1) {
            int y = __shfl_up_sync(0xFFFFFFFFu, s, o);
            if (lane >= o) s += y;
        }
        if (lane < 8) wsum[lane] = s;
    }
    __syncthreads();
    int incl = x + ((w > 0) ? wsum[w - 1] : 0);
    int block_total = wsum[7];

    __shared__ int s_prefix;
    if (t == 0) {
        if (b == 0) {
            g_scan_inc[0] = block_total;
            __threadfence();
            atomicExch(&g_scan_flag[0], 2);
            s_prefix = 0;
        } else {
            g_scan_agg[b] = block_total;
            __threadfence();
            atomicExch(&g_scan_flag[b], 1);
            int sum = 0;
            for (int j = b - 1; j >= 0; j--) {
                int f;
                do { f = atomicAdd(&g_scan_flag[j], 0); } while (f == 0);
                if (f == 2) { sum += atomicAdd(&g_scan_inc[j], 0); break; }
                sum += atomicAdd(&g_scan_agg[j], 0);
            }
            g_scan_inc[b] = sum + block_total;
            __threadfence();
            atomicExch(&g_scan_flag[b], 2);
            s_prefix = sum;
        }
    }
    __syncthreads();

    int excl = s_prefix + incl - v;
    if (idx < n_nodes) g_off[idx] = excl;
    if (idx == n_nodes) g_off[n_nodes] = n_edges;
}

// atomic-free permutation scatter, 4 edges per thread for MLP
__global__ void __launch_bounds__(256)
scatter_perm_kernel(const int* __restrict__ src,
                    const int* __restrict__ dst, int n_edges) {
    int base = (blockIdx.x * blockDim.x + threadIdx.x) * 4;
    if (base + 4 <= n_edges) {
        int d0 = dst[base], d1 = dst[base+1], d2 = dst[base+2], d3 = dst[base+3];
        int r0 = g_rank[base], r1 = g_rank[base+1], r2 = g_rank[base+2], r3 = g_rank[base+3];
        int s0 = src[base], s1 = src[base+1], s2 = src[base+2], s3 = src[base+3];
        int o0 = g_off[d0], o1 = g_off[d1], o2 = g_off[d2], o3 = g_off[d3];
        g_pidx[o0 + r0] = make_int2(s0, base);
        g_pidx[o1 + r1] = make_int2(s1, base + 1);
        g_pidx[o2 + r2] = make_int2(s2, base + 2);
        g_pidx[o3 + r3] = make_int2(s3, base + 3);
    } else {
        for (int e = base; e < n_edges; e++)
            g_pidx[g_off[dst[e]] + g_rank[e]] = make_int2(src[e], e);
    }
}

// ---------------------------------------------------------------------------
// Fused per-node kernel, online softmax, register-resident edge indices.
//   Per 32-edge chunk: lane loads pidx[beg+lane] once; edge (src,eid) come
//   from shfl broadcasts. Edge loop unrolled x4 -> 8 LDG.128 in flight.
// ---------------------------------------------------------------------------
__global__ void __launch_bounds__(256)
fused_node_kernel(const float* __restrict__ h_v,
                  const float* __restrict__ h_d,
                  const float* __restrict__ W_pi,
                  const float* __restrict__ W_M,
                  float*       __restrict__ out,
                  int n_nodes)
{
    int lane = threadIdx.x & 31;

    const float4* __restrict__ hv4 = (const float4*)h_v;
    const float4* __restrict__ hd4 = (const float4*)h_d;
    float4 wp = ((const float4*)W_pi)[lane];
    float4 w1 = ((const float4*)W_M)[lane];
    float4 w2 = ((const float4*)(W_M + DIM))[lane];

    while (true) {
        int node;
        if (lane == 0) node = atomicAdd(&g_work, 1);
        node = __shfl_sync(0xFFFFFFFFu, node, 0);
        if (node >= n_nodes) break;

        int beg = g_off[node];
        int deg = g_off[node + 1] - beg;

        float4 acc = make_float4(0.f, 0.f, 0.f, 0.f);
        float mx = -3.4e38f, sum = 0.f;

        if (deg > 0) {
            float4 fd = hv4[(size_t)node * 32 + lane];
            float4 c1 = make_float4(fd.x * wp.x, fd.y * wp.y, fd.z * wp.z, fd.w * wp.w);
            float4 c2 = make_float4(fd.x * w1.x, fd.y * w1.y, fd.z * w1.z, fd.w * w1.w);

            for (int base = 0; base < deg; base += 32) {
                int cnt = min(32, deg - base);
                // one load covers up to 32 edges' indices
                int2 p = (lane < cnt) ? g_pidx[beg + base + lane]
                                      : make_int2(0, 0);

                int i = 0;
                for (; i + 4 <= cnt; i += 4) {
                    float4 fs[4], hd[4];
                    #pragma unroll
                    for (int j = 0; j < 4; j++) {
                        int s = __shfl_sync(0xFFFFFFFFu, p.x, i + j);
                        int e = __shfl_sync(0xFFFFFFFFu, p.y, i + j);
                        fs[j] = hv4[(size_t)s * 32 + lane];
                        hd[j] = hd4[(size_t)e * 32 + lane];
                    }
                    float d1[4], d2[4];
                    #pragma unroll
                    for (int j = 0; j < 4; j++) {
                        d1[j] = fs[j].x * hd[j].x * c1.x + fs[j].y * hd[j].y * c1.y
                              + fs[j].z * hd[j].z * c1.z + fs[j].w * hd[j].w * c1.w;
                        d2[j] = fs[j].x * c2.x + fs[j].y * c2.y
                              + fs[j].z * c2.z + fs[j].w * c2.w
                              + hd[j].x * w2.x + hd[j].y * w2.y
                              + hd[j].z * w2.z + hd[j].w * w2.w;
                    }
                    #pragma unroll
                    for (int o = 16; o; o >>= 1) {
                        #pragma unroll
                        for (int j = 0; j < 4; j++) {
                            d1[j] += __shfl_xor_sync(0xFFFFFFFFu, d1[j], o);
                            d2[j] += __shfl_xor_sync(0xFFFFFFFFu, d2[j], o);
                        }
                    }
                    float l[4], ev[4];
                    #pragma unroll
                    for (int j = 0; j < 4; j++)
                        l[j] = d1[j] * (1.0f / (1.0f + __expf(-d2[j])));

                    float m2 = fmaxf(fmaxf(l[0], l[1]), fmaxf(l[2], l[3]));
                    m2 = fmaxf(mx, m2);
                    float sc = __expf(mx - m2);
                    #pragma unroll
                    for (int j = 0; j < 4; j++) ev[j] = __expf(l[j] - m2);
                    sum = sum * sc + ev[0] + ev[1] + ev[2] + ev[3];
                    acc.x = acc.x * sc + fs[0].x * ev[0] + fs[1].x * ev[1]
                                       + fs[2].x * ev[2] + fs[3].x * ev[3];
                    acc.y = acc.y * sc + fs[0].y * ev[0] + fs[1].y * ev[1]
                                       + fs[2].y * ev[2] + fs[3].y * ev[3];
                    acc.z = acc.z * sc + fs[0].z * ev[0] + fs[1].z * ev[1]
                                       + fs[2].z * ev[2] + fs[3].z * ev[3];
                    acc.w = acc.w * sc + fs[0].w * ev[0] + fs[1].w * ev[1]
                                       + fs[2].w * ev[2] + fs[3].w * ev[3];
                    mx = m2;
                }
                // tail edges of chunk
                for (; i < cnt; i++) {
                    int s = __shfl_sync(0xFFFFFFFFu, p.x, i);
                    int e = __shfl_sync(0xFFFFFFFFu, p.y, i);
                    float4 fsA = hv4[(size_t)s * 32 + lane];
                    float4 hdA = hd4[(size_t)e * 32 + lane];
                    float a1 = fsA.x * hdA.x * c1.x + fsA.y * hdA.y * c1.y
                             + fsA.z * hdA.z * c1.z + fsA.w * hdA.w * c1.w;
                    float a2 = fsA.x * c2.x + fsA.y * c2.y + fsA.z * c2.z + fsA.w * c2.w
                             + hdA.x * w2.x + hdA.y * w2.y + hdA.z * w2.z + hdA.w * w2.w;
                    #pragma unroll
                    for (int o = 16; o; o >>= 1) {
                        a1 += __shfl_xor_sync(0xFFFFFFFFu, a1, o);
                        a2 += __shfl_xor_sync(0xFFFFFFFFu, a2, o);
                    }
                    float lA = a1 * (1.0f / (1.0f + __expf(-a2)));
                    float m2 = fmaxf(mx, lA);
                    float sc = __expf(mx - m2);
                    float eA = __expf(lA - m2);
                    sum = sum * sc + eA;
                    acc.x = acc.x * sc + fsA.x * eA;
                    acc.y = acc.y * sc + fsA.y * eA;
                    acc.z = acc.z * sc + fsA.z * eA;
                    acc.w = acc.w * sc + fsA.w * eA;
                    mx = m2;
                }
            }

            float inv = 1.0f / sum;
            acc.x *= inv; acc.y *= inv; acc.z *= inv; acc.w *= inv;
        }

        ((float4*)out)[(size_t)node * 32 + lane] = acc;
    }
}

// ---------------------------------------------------------------------------
// Launch
// inputs: 0=h_v [N,128] f32, 1=h_d [E,128] f32, 2=W_pi [128,1] f32,
//         3=W_M [256,1] f32, 4=src [E] i32, 5=dst [E] i32 ; out [N,128] f32
// ---------------------------------------------------------------------------
extern "C" void kernel_launch(void* const* d_in, const int* in_sizes, int n_in,
                              void* d_out, int out_size)
{
    const float* h_v  = (const float*)d_in[0];
    const float* h_d  = (const float*)d_in[1];
    const float* W_pi = (const float*)d_in[2];
    const float* W_M  = (const float*)d_in[3];
    const int*   src  = (const int*)d_in[4];
    const int*   dst  = (const int*)d_in[5];
    float*       out  = (float*)d_out;

    int n_nodes = in_sizes[0] / DIM;
    int n_edges = in_sizes[1] / DIM;
    int node_blocks = (n_nodes + 255) / 256;

    zero_kernel<<<node_blocks, 256>>>(n_nodes);
    hist_kernel<<<(n_edges + 255) / 256, 256>>>(dst, n_edges);
    scan_kernel<<<node_blocks, 256>>>(n_nodes, n_edges);
    scatter_perm_kernel<<<(n_edges / 4 + 255) / 256 + 1, 256>>>(src, dst, n_edges);

    fused_node_kernel<<<1024, 256>>>(h_v, h_d, W_pi, W_M, out, n_nodes);
}